// round 8
// baseline (speedup 1.0000x reference)
#include <cuda_runtime.h>
#include <cuda_bf16.h>
#include <cstdint>
#include <cstddef>

// Shape fixed by setup_inputs: B=64, S=2048, D=512, fp32.
// Outputs flattened: d_prime [64*512], probs [64*2048], logit [64*2048].
#define B_ 64
#define S_ 2048
#define D_ 512
#define CCLIP 10.0f
#define OUT_DP 0
#define OUT_PROBS (B_ * D_)
#define OUT_LOGIT (B_ * D_ + B_ * S_)

// ---- static device scratch (no allocations allowed) ----
__device__ float g_q[B_ * D_];            // q = tgt @ W_q^T
__device__ float g_u[B_ * S_];            // u logits pre-clip
__device__ float g_dppart[32 * B_ * D_];  // d' partials (32 s-chunks)
// W_ref hi/lo bf16, 32 slices in consumption order j = n*8 + ks64.
// Slice = 128 d-rows x 64 k, row = 128B, SW128-swizzled. 16KB each.
__device__ __align__(16) unsigned char g_wh[32 * 16384];
__device__ __align__(16) unsigned char g_wl[32 * 16384];

__device__ __forceinline__ uint32_t smem_u32(const void* p) {
    uint32_t a;
    asm("{ .reg .u64 t; cvta.to.shared.u64 t, %1; cvt.u32.u64 %0, t; }"
        : "=r"(a) : "l"(p));
    return a;
}
__device__ __forceinline__ uint32_t swz(uint32_t o) { return o ^ ((o >> 3) & 0x70); }

__device__ __forceinline__ void ldsm4(uint32_t* r, uint32_t addr) {
    asm volatile("ldmatrix.sync.aligned.m8n8.x4.shared.b16 {%0,%1,%2,%3}, [%4];"
        : "=r"(r[0]), "=r"(r[1]), "=r"(r[2]), "=r"(r[3]) : "r"(addr));
}
__device__ __forceinline__ void mma16816(float* c, const uint32_t* a,
                                         const uint32_t* b) {
    asm volatile(
        "mma.sync.aligned.m16n8k16.row.col.f32.bf16.bf16.f32 "
        "{%0,%1,%2,%3}, {%4,%5,%6,%7}, {%8,%9}, {%0,%1,%2,%3};"
        : "+f"(c[0]), "+f"(c[1]), "+f"(c[2]), "+f"(c[3])
        : "r"(a[0]), "r"(a[1]), "r"(a[2]), "r"(a[3]), "r"(b[0]), "r"(b[1]));
}
__device__ __forceinline__ void cp16(uint32_t saddr, const void* g) {
    asm volatile("cp.async.cg.shared.global [%0], [%1], 16;"
        :: "r"(saddr), "l"(g));
}
#define CP_COMMIT() asm volatile("cp.async.commit_group;" ::: "memory")
#define CP_WAIT1()  asm volatile("cp.async.wait_group 1;" ::: "memory")

__device__ __forceinline__ float fast_tanh(float x) {
    float e = __expf(2.0f * x);
    return 1.0f - __fdividef(2.0f, e + 1.0f);
}

// ===================================================================
// Kernel A: q[b,d] = sum_k tgt[b,k] * W_q[d,k]  (tiny)
// ===================================================================
__global__ void qproj_kernel(const float* __restrict__ tgt,
                             const float* __restrict__ Wq) {
    __shared__ float wrow[D_];
    const int d = blockIdx.x;
    for (int i = threadIdx.x; i < D_; i += blockDim.x) wrow[i] = Wq[d * D_ + i];
    __syncthreads();
    const int warp = threadIdx.x >> 5, lane = threadIdx.x & 31;
    for (int b = warp; b < B_; b += 8) {
        const float* t = tgt + b * D_;
        float p = 0.f;
        #pragma unroll 4
        for (int k = lane; k < D_; k += 32) p += t[k] * wrow[k];
        #pragma unroll
        for (int o = 16; o; o >>= 1) p += __shfl_xor_sync(0xffffffffu, p, o);
        if (lane == 0) g_q[b * D_ + d] = p;
    }
}

// ===================================================================
// Kernel W: split W_ref into hi/lo bf16 slices, pre-swizzled.
// ===================================================================
__global__ void wsplit_kernel(const float* __restrict__ Wref) {
    const int i = blockIdx.x * blockDim.x + threadIdx.x;  // 0 .. 262143
    const float w = Wref[i];
    const int d = i >> 9, k = i & 511;
    const int n = d >> 7, r = d & 127;
    const int ks = k >> 6, c = k & 63;
    const size_t off = (size_t)(n * 8 + ks) * 16384 + swz((uint32_t)(r * 128 + c * 2));
    __nv_bfloat16 hi = __float2bfloat16(w);
    *(__nv_bfloat16*)(g_wh + off) = hi;
    *(__nv_bfloat16*)(g_wl + off) = __float2bfloat16(w - __bfloat162float(hi));
}

// ===================================================================
// Kernel B: split-bf16 mma.sync GEMM + fused tanh/v-reduction.
// CTA = (b, 64-row s-tile). A (64x512 hi/lo) resident in smem, converted
// once. B streamed in 32 slices (n-major) via 2-stage cp.async ring.
// 8 warps = 2(warp_m: 32 s-rows) x 2(warp_n: 64 d) x 2(warp_k: 32 k).
// Fused 3-term mma (ah*bh + ah*bl + al*bh) per fragment load.
// k-split partial preacts merged in smem before the tanh epilogue.
// ===================================================================
#define SM_A_H   0
#define SM_A_L   65536
#define SM_B     131072
#define SM_MERGE 196608
#define SM_SQ    214016
#define SM_SV    216064
#define SM_U     218112
#define SM_TOTAL 218624

__device__ __forceinline__ void prefetchB(uint32_t sb, int j, int tid) {
    const uint32_t dst = sb + SM_B + (uint32_t)(j & 1) * 32768 + tid * 16;
    const unsigned char* sh = g_wh + (size_t)j * 16384 + tid * 16;
    const unsigned char* sl = g_wl + (size_t)j * 16384 + tid * 16;
    #pragma unroll
    for (int q = 0; q < 4; ++q) {
        cp16(dst + q * 4096, sh + q * 4096);
        cp16(dst + 16384 + q * 4096, sl + q * 4096);
    }
}

__global__ __launch_bounds__(256)
void fused_mma_kernel(const float* __restrict__ src,
                      const float* __restrict__ v) {
    extern __shared__ char smem[];
    const uint32_t sb = smem_u32(smem);
    const int tid = threadIdx.x, wid = tid >> 5, lane = tid & 31;
    const int warp_n = wid & 1, warp_m = (wid >> 1) & 1, warp_k = wid >> 2;
    const int sz = blockIdx.x, b = blockIdx.y;

    float* sq = (float*)(smem + SM_SQ);
    float* sv = (float*)(smem + SM_SV);
    float* u_sm = (float*)(smem + SM_U);
    float4* mbuf = (float4*)(smem + SM_MERGE);   // 2 warp_n slots x 32 x 17
    for (int i = tid; i < D_; i += 256) {
        sq[i] = g_q[b * D_ + i];
        sv[i] = v[i];
    }
    if (tid < 128) u_sm[tid] = 0.f;

    // kick off B slices 0,1
    prefetchB(sb, 0, tid); CP_COMMIT();
    prefetchB(sb, 1, tid); CP_COMMIT();

    // ---- convert A (64 rows x K=512) fp32 -> hi/lo bf16, once ----
    const float* srcB = src + ((size_t)(b * S_ + sz * 64)) * D_;
    #pragma unroll 4
    for (int it = 0; it < 32; ++it) {
        const int idx = tid + it * 256;          // 0..8191 float4s
        const int r = idx >> 7, f4 = idx & 127;
        const int k0 = f4 * 4, sl = k0 >> 6, c = k0 & 63;
        float4 x = *(const float4*)(srcB + (size_t)r * D_ + k0);
        const uint32_t ob = (uint32_t)sl * 8192 + swz((uint32_t)(r * 128 + c * 2));
        __nv_bfloat162 h0 = __floats2bfloat162_rn(x.x, x.y);
        __nv_bfloat162 h1 = __floats2bfloat162_rn(x.z, x.w);
        *(__nv_bfloat162*)(smem + SM_A_H + ob) = h0;
        *(__nv_bfloat162*)(smem + SM_A_H + ob + 4) = h1;
        float lx = x.x - __low2float(h0), ly = x.y - __high2float(h0);
        float lz = x.z - __low2float(h1), lw = x.w - __high2float(h1);
        *(__nv_bfloat162*)(smem + SM_A_L + ob) = __floats2bfloat162_rn(lx, ly);
        *(__nv_bfloat162*)(smem + SM_A_L + ob + 4) = __floats2bfloat162_rn(lz, lw);
    }

    // lane-invariant fragment byte offsets (pre-swizzle)
    // A: rows warp_m*32 + mt*16 + (lane&15); k: warp_k*64B + ks*32B + (lane>>4)*16B
    const uint32_t laneA0 = (uint32_t)((warp_m * 32 + (lane & 15)) * 128 +
                                       (lane >> 4) * 16 + warp_k * 64);
    // B: rows warp_n*64 + ntp*16 + (lane&7)+((lane>>4)&1)*8; k: warp_k*64B + ks*32B + ((lane>>3)&1)*16B
    const uint32_t laneB0 = (uint32_t)((warp_n * 64 + (lane & 7) + ((lane >> 4) & 1) * 8) * 128 +
                                       ((lane >> 3) & 1) * 16 + warp_k * 64);

    float acc[2][8][4];                           // [mt][2*ntp+half][e]
    float* accf = &acc[0][0][0];
    #pragma unroll
    for (int t = 0; t < 64; ++t) accf[t] = 0.f;

    for (int i = 0; i < 32; ++i) {
        const int n = i >> 3, sl = i & 7;
        CP_WAIT1();
        __syncthreads();   // slice i visible; prior compute done

        const uint32_t aH = sb + SM_A_H + (uint32_t)sl * 8192;
        const uint32_t aL = sb + SM_A_L + (uint32_t)sl * 8192;
        const uint32_t bH = sb + SM_B + (uint32_t)(i & 1) * 32768;
        const uint32_t bL = bH + 16384;

        #pragma unroll
        for (int ks = 0; ks < 2; ++ks) {
            uint32_t ah[2][4], al[2][4];
            #pragma unroll
            for (int mt = 0; mt < 2; ++mt) {
                const uint32_t ao = swz(laneA0 + (uint32_t)mt * 2048 + (uint32_t)ks * 32);
                ldsm4(ah[mt], aH + ao);
                ldsm4(al[mt], aL + ao);
            }
            #pragma unroll
            for (int ntp = 0; ntp < 4; ++ntp) {
                uint32_t bh[4], bl[4];
                const uint32_t bo = swz(laneB0 + (uint32_t)ntp * 2048 + (uint32_t)ks * 32);
                ldsm4(bh, bH + bo);
                ldsm4(bl, bL + bo);
                #pragma unroll
                for (int mt = 0; mt < 2; ++mt) {
                    float* c0 = acc[mt][2 * ntp];
                    float* c1 = acc[mt][2 * ntp + 1];
                    mma16816(c0, ah[mt], bh);
                    mma16816(c1, ah[mt], bh + 2);
                    mma16816(c0, ah[mt], bl);
                    mma16816(c1, ah[mt], bl + 2);
                    mma16816(c0, al[mt], bh);
                    mma16816(c1, al[mt], bh + 2);
                }
            }
        }

        if (sl == 7) {
            // ---- merge k-split partials, then tanh/v epilogue, 2 rounds ----
            #pragma unroll
            for (int rm = 0; rm < 2; ++rm) {
                __syncthreads();
                if (warp_m == rm && warp_k == 1) {
                    float4* dst = mbuf + (warp_n * 32 + lane) * 17;
                    #pragma unroll
                    for (int t = 0; t < 16; ++t) dst[t] = ((float4*)accf)[t];
                }
                __syncthreads();
                if (warp_m == rm && warp_k == 0) {
                    const float4* srcp = mbuf + (warp_n * 32 + lane) * 17;
                    #pragma unroll
                    for (int t = 0; t < 16; ++t) {
                        float4 x = srcp[t];
                        accf[t * 4 + 0] += x.x;
                        accf[t * 4 + 1] += x.y;
                        accf[t * 4 + 2] += x.z;
                        accf[t * 4 + 3] += x.w;
                    }
                    const int g = lane >> 2;
                    #pragma unroll
                    for (int mt = 0; mt < 2; ++mt) {
                        float s0 = 0.f, s1 = 0.f;
                        #pragma unroll
                        for (int nt = 0; nt < 8; ++nt) {
                            const int d = n * 128 + warp_n * 64 + nt * 8 + (lane & 3) * 2;
                            const float* c = acc[mt][nt];
                            s0 += sv[d] * fast_tanh(sq[d] + c[0])
                                + sv[d + 1] * fast_tanh(sq[d + 1] + c[1]);
                            s1 += sv[d] * fast_tanh(sq[d] + c[2])
                                + sv[d + 1] * fast_tanh(sq[d + 1] + c[3]);
                        }
                        s0 += __shfl_xor_sync(0xffffffffu, s0, 1);
                        s0 += __shfl_xor_sync(0xffffffffu, s0, 2);
                        s1 += __shfl_xor_sync(0xffffffffu, s1, 1);
                        s1 += __shfl_xor_sync(0xffffffffu, s1, 2);
                        if ((lane & 3) == 0) {
                            const int r0 = warp_m * 32 + mt * 16 + g;
                            u_sm[warp_n * 64 + r0] += s0;
                            u_sm[warp_n * 64 + r0 + 8] += s1;
                        }
                    }
                }
            }
            #pragma unroll
            for (int t = 0; t < 64; ++t) accf[t] = 0.f;
        }

        __syncthreads();   // all warps done reading buf (i&1)
        if (i < 30) prefetchB(sb, i + 2, tid);
        CP_COMMIT();       // unconditional: keeps group arithmetic uniform
    }

    __syncthreads();
    if (tid < 64)
        g_u[b * S_ + sz * 64 + tid] = u_sm[tid] + u_sm[tid + 64];
}

// ===================================================================
// Kernel C: logit = C*tanh(u); softmax over S (shift by constant C).
// ===================================================================
__global__ void softmax_kernel(float* __restrict__ out) {
    const int b = blockIdx.x, tid = threadIdx.x;
    float* logit = out + OUT_LOGIT + b * S_;
    float* probs = out + OUT_PROBS + b * S_;
    __shared__ float red[256];

    float lsum = 0.f;
    for (int s = tid; s < S_; s += 256) {
        const float l = CCLIP * fast_tanh(g_u[b * S_ + s]);
        logit[s] = l;
        lsum += expf(l - CCLIP);
    }
    red[tid] = lsum;
    __syncthreads();
    for (int o = 128; o; o >>= 1) {
        if (tid < o) red[tid] += red[tid + o];
        __syncthreads();
    }
    const float inv = 1.f / red[0];
    for (int s = tid; s < S_; s += 256)
        probs[s] = expf(logit[s] - CCLIP) * inv;
}

// ===================================================================
// Kernel D: d' partials; 32 s-chunks of 64 rows, float4, deterministic.
// ===================================================================
__global__ void dprime_kernel(const float* __restrict__ src,
                              const float* __restrict__ out) {
    const float* probs = out + OUT_PROBS;
    const int sc = blockIdx.x, b = blockIdx.y, t = threadIdx.x;  // t: 0..127
    __shared__ float p_sm[64];
    if (t < 64) p_sm[t] = probs[b * S_ + sc * 64 + t];
    __syncthreads();
    const float4* sp = (const float4*)(src + ((size_t)(b * S_ + sc * 64)) * D_) + t;
    float4 acc = make_float4(0.f, 0.f, 0.f, 0.f);
    #pragma unroll 8
    for (int s = 0; s < 64; ++s) {
        float4 x = sp[(size_t)s * 128];
        const float p = p_sm[s];
        acc.x += p * x.x; acc.y += p * x.y;
        acc.z += p * x.z; acc.w += p * x.w;
    }
    *(float4*)(g_dppart + ((size_t)sc * B_ + b) * D_ + t * 4) = acc;
}

__global__ void dpsum_kernel(float* __restrict__ out) {
    const int b = blockIdx.x, d = threadIdx.x;
    float acc = 0.f;
    #pragma unroll
    for (int sc = 0; sc < 32; ++sc)
        acc += g_dppart[((size_t)sc * B_ + b) * D_ + d];
    out[OUT_DP + b * D_ + d] = acc;
}

// ===================================================================
extern "C" void kernel_launch(void* const* d_in, const int* in_sizes, int n_in,
                              void* d_out, int out_size) {
    const float* src  = (const float*)d_in[0];  // [64, 2048, 512]
    const float* tgt  = (const float*)d_in[1];  // [64, 1, 512]
    const float* Wq   = (const float*)d_in[2];  // [512, 512]
    const float* Wref = (const float*)d_in[3];  // [512, 512]
    const float* v    = (const float*)d_in[4];  // [512]
    float* out = (float*)d_out;

    qproj_kernel<<<D_, 256>>>(tgt, Wq);
    wsplit_kernel<<<512, 512>>>(Wref);

    cudaFuncSetAttribute(fused_mma_kernel,
                         cudaFuncAttributeMaxDynamicSharedMemorySize, SM_TOTAL);
    fused_mma_kernel<<<dim3(32, B_), 256, SM_TOTAL>>>(src, v);

    softmax_kernel<<<B_, 256>>>(out);

    dprime_kernel<<<dim3(32, B_), 128>>>(src, out);
    dpsum_kernel<<<B_, D_>>>(out);
}